// round 13
// baseline (speedup 1.0000x reference)
#include <cuda_runtime.h>
#include <cstdint>

// Problem constants
#define T_STEPS 1024
#define Hn      100
#define HROW    128   // padded h row stride (slots 0..99 valid, 100..127 pad)
#define BB      4     // batch rows per block
#define NTHREADS 256  // 128 ln-slots * 2 kc (8 warps, 2/SMSP -> reg cap 256)
#define NBLOCKS  128
#define BTOT     512

typedef unsigned long long ull;

// Scratch for h history: [t][n][b]  (~210MB, static .bss)
__device__ float g_hscr[T_STEPS][Hn][BTOT];

// ---------- f32x2 packed-math helpers ----------
__device__ __forceinline__ ull pack2(float lo, float hi) {
    ull r; asm("mov.b64 %0, {%1, %2};" : "=l"(r) : "f"(lo), "f"(hi)); return r;
}
__device__ __forceinline__ void unpack2(ull v, float& lo, float& hi) {
    asm("mov.b64 {%0, %1}, %2;" : "=f"(lo), "=f"(hi) : "l"(v));
}
__device__ __forceinline__ ull ffma2(ull a, ull b, ull c) {
    ull d; asm("fma.rn.f32x2 %0, %1, %2, %3;" : "=l"(d) : "l"(a), "l"(b), "l"(c)); return d;
}
__device__ __forceinline__ ull fadd2(ull a, ull b) {
    ull d; asm("add.rn.f32x2 %0, %1, %2;" : "=l"(d) : "l"(a), "l"(b)); return d;
}

// ---------- fast transcendentals (MUFU, ~1e-6 rel err) ----------
__device__ __forceinline__ float ex2a(float x) {
    float y; asm("ex2.approx.ftz.f32 %0, %1;" : "=f"(y) : "f"(x)); return y;
}
__device__ __forceinline__ float rcpa(float x) {
    float y; asm("rcp.approx.ftz.f32 %0, %1;" : "=f"(y) : "f"(x)); return y;
}

// Interleaved h layout inside one batch row (valid k packed into idx 0..99):
//   k = q*50 + r (q = k-half 0/1):
//     r < 48 : idx = (r/4)*8 + q*4 + (r%4)   (12 float4 chunks per half)
//     r >= 48: idx = 96 + q*2 + (r-48)        (float2 tail)
__device__ __forceinline__ int h_idx_of_k(int k) {
    int q = k / 50, r = k % 50;
    return (r < 48) ? ((r >> 2) * 8 + q * 4 + (r & 3)) : (96 + q * 2 + (r - 48));
}

// Thread layout: tid = ln*2 + kc, ln in [0,128) (ln>=100 inert), kc = k-half.
// Lane kc owns batches {2kc, 2kc+1} (two c-states in registers).
// 8 warps -> 2/SMSP -> reg cap 256: all 200 weight regs resident.
// FFMA2 floor: 2 warps x 400 inst x rt3 (3 distinct regs/bank) = 2400 cyc/SMSP.
__global__ void __launch_bounds__(NTHREADS, 1)
lstm_persistent_kernel(const float* __restrict__ input,   // [512][1024]
                       const float* __restrict__ W_ih,    // [400]
                       const float* __restrict__ W_hh,    // [400][100]
                       const float* __restrict__ b_ih,    // [400]
                       const float* __restrict__ b_hh)    // [400]
{
    __shared__ __align__(16) float h2[2][BB][HROW];        // double buffered
    __shared__ __align__(16) ulonglong2 s_gp1[128];        // {wih(i,f), bias(i,f)}
    __shared__ __align__(16) ulonglong2 s_gp2[128];        // {wih(g,o), bias(g,o)}

    const int tid  = threadIdx.x;
    const int ln   = tid >> 1;
    const int kc   = tid & 1;
    const bool valid = (ln < Hn);
    const int n = ln;
    const int nsafe = valid ? n : 0;
    const int bbase = blockIdx.x * BB;

    // ---- register-stationary weights: 25 k-pairs per gate (50 = 2*25) ----
    ull w[4][25];
    #pragma unroll
    for (int g = 0; g < 4; ++g) {
        const float* row = W_hh + (g * Hn + nsafe) * Hn;
        #pragma unroll
        for (int j = 0; j < 25; ++j) {
            const int k0 = kc * 50 + 2 * j;
            w[g][j] = valid ? pack2(row[k0], row[k0 + 1]) : 0ULL;
        }
    }
    // per-n wih/bias tables in SMEM
    if (kc == 0) {
        float wi = valid ? W_ih[n]            : 0.f;
        float wf = valid ? W_ih[Hn + n]       : 0.f;
        float wg = valid ? W_ih[2 * Hn + n]   : 0.f;
        float wo = valid ? W_ih[3 * Hn + n]   : 0.f;
        float bi = valid ? b_ih[n]          + b_hh[n]          : 0.f;
        float bf = valid ? b_ih[Hn + n]     + b_hh[Hn + n]     : 0.f;
        float bg = valid ? b_ih[2 * Hn + n] + b_hh[2 * Hn + n] : 0.f;
        float bo = valid ? b_ih[3 * Hn + n] + b_hh[3 * Hn + n] : 0.f;
        s_gp1[ln] = make_ulonglong2(pack2(wi, wf), pack2(bi, bf));
        s_gp2[ln] = make_ulonglong2(pack2(wg, wo), pack2(bg, bo));
    }

    // zero both h buffers
    for (int i = tid; i < 2 * BB * HROW; i += NTHREADS)
        (&h2[0][0][0])[i] = 0.0f;

    float c0 = 0.0f, c1 = 0.0f;     // c-states for owned batches 2kc, 2kc+1
    const float* __restrict__ xptrA = input + (bbase + 2 * kc) * T_STEPS;
    const float* __restrict__ xptrB = xptrA + T_STEPS;
    const int widx = valid ? h_idx_of_k(n) : ln;   // pads 100..111 for warp 6
    float* __restrict__ sptr = &g_hscr[0][nsafe][bbase + 2 * kc];

    // x double-buffer prefetch (hides LDG line-fill misses off the gate path)
    float xa_cur = xptrA[0];
    float xb_cur = xptrB[0];

    __syncthreads();

    for (int t = 0; t < T_STEPS; ++t) {
        const int p = t & 1;
        if (ln < 112) {   // warp 7 fully inert: skip body, keep barrier
            // prefetch next step's x immediately (consumed ~2000 cyc later)
            const int tn = (t + 1) & (T_STEPS - 1);
            const float xa_nxt = xptrA[tn];
            const float xb_nxt = xptrB[tn];

            const float* __restrict__ hb = &h2[p][0][0];

            ull G01[2], G23[2];
            #pragma unroll
            for (int b = 0; b < BB; ++b) {
                const float* rowp = hb + b * HROW;
                const ulonglong2* v =
                    reinterpret_cast<const ulonglong2*>(rowp + kc * 4);
                ull a0 = 0, a1 = 0, a2 = 0, a3 = 0;
                #pragma unroll
                for (int j = 0; j < 12; ++j) {
                    const ulonglong2 hp = v[j * 2];   // k-pairs 2j, 2j+1
                    a0 = ffma2(w[0][2 * j], hp.x, a0);
                    a1 = ffma2(w[1][2 * j], hp.x, a1);
                    a2 = ffma2(w[2][2 * j], hp.x, a2);
                    a3 = ffma2(w[3][2 * j], hp.x, a3);
                    a0 = ffma2(w[0][2 * j + 1], hp.y, a0);
                    a1 = ffma2(w[1][2 * j + 1], hp.y, a1);
                    a2 = ffma2(w[2][2 * j + 1], hp.y, a2);
                    a3 = ffma2(w[3][2 * j + 1], hp.y, a3);
                }
                // tail k-pair (r = 48,49) at idx 96 + kc*2
                const ull ht = *reinterpret_cast<const ull*>(rowp + 96 + kc * 2);
                a0 = ffma2(w[0][24], ht, a0);
                a1 = ffma2(w[1][24], ht, a1);
                a2 = ffma2(w[2][24], ht, a2);
                a3 = ffma2(w[3][24], ht, a3);
                // fold k-pair lanes, pack by gate pairs
                float lo, hi, s0, s1, s2, s3;
                unpack2(a0, lo, hi); s0 = lo + hi;
                unpack2(a1, lo, hi); s1 = lo + hi;
                unpack2(a2, lo, hi); s2 = lo + hi;
                unpack2(a3, lo, hi); s3 = lo + hi;
                const ull p01 = pack2(s0, s1);
                const ull p23 = pack2(s2, s3);
                // single xor-1 exchange with the other k-half
                const ull r01 = __shfl_xor_sync(0xffffffffu, p01, 1);
                const ull r23 = __shfl_xor_sync(0xffffffffu, p23, 1);
                if ((b >> 1) == kc) {
                    G01[b & 1] = fadd2(p01, r01);
                    G23[b & 1] = fadd2(p23, r23);
                }
            }

            // ---- gates for owned batches, interleaved for max MUFU ILP ----
            const ulonglong2 gp1 = s_gp1[ln];
            const ulonglong2 gp2 = s_gp2[ln];
            const ull xva = pack2(xa_cur, xa_cur);
            const ull xvb = pack2(xb_cur, xb_cur);
            const ull A0 = ffma2(xva, gp1.x, fadd2(G01[0], gp1.y));
            const ull B0 = ffma2(xva, gp2.x, fadd2(G23[0], gp2.y));
            const ull A1 = ffma2(xvb, gp1.x, fadd2(G01[1], gp1.y));
            const ull B1 = ffma2(xvb, gp2.x, fadd2(G23[1], gp2.y));
            float gi0, gf0, gg0, go0, gi1, gf1, gg1, go1;
            unpack2(A0, gi0, gf0); unpack2(B0, gg0, go0);
            unpack2(A1, gi1, gf1); unpack2(B1, gg1, go1);

            // batch all 8 ex2 (independent), then the rcp wave
            const float L1E = 1.4426950408889634f;
            const float ei0 = ex2a(-L1E * gi0);
            const float ef0 = ex2a(-L1E * gf0);
            const float eg0 = ex2a(-2.0f * L1E * gg0);
            const float eo0 = ex2a(-L1E * go0);
            const float ei1 = ex2a(-L1E * gi1);
            const float ef1 = ex2a(-L1E * gf1);
            const float eg1 = ex2a(-2.0f * L1E * gg1);
            const float eo1 = ex2a(-L1E * go1);
            const float ig0 = rcpa(1.0f + ei0);
            const float fg0 = rcpa(1.0f + ef0);
            const float tg0 = fmaf(2.0f, rcpa(1.0f + eg0), -1.0f);
            const float og0 = rcpa(1.0f + eo0);
            const float ig1 = rcpa(1.0f + ei1);
            const float fg1 = rcpa(1.0f + ef1);
            const float tg1 = fmaf(2.0f, rcpa(1.0f + eg1), -1.0f);
            const float og1 = rcpa(1.0f + eo1);

            c0 = fmaf(fg0, c0, ig0 * tg0);
            c1 = fmaf(fg1, c1, ig1 * tg1);
            const float ec0 = ex2a(-2.0f * L1E * c0);
            const float ec1 = ex2a(-2.0f * L1E * c1);
            const float h0 = og0 * fmaf(2.0f, rcpa(1.0f + ec0), -1.0f);
            const float h1 = og1 * fmaf(2.0f, rcpa(1.0f + ec1), -1.0f);

            // publish h into next buffer (rows = owned batches)
            float* hw = &h2[p ^ 1][0][0];
            hw[(2 * kc)     * HROW + widx] = h0;
            hw[(2 * kc + 1) * HROW + widx] = h1;
            // stream h history: one STG.64 (adjacent batches)
            if (valid)
                *reinterpret_cast<ull*>(sptr) = pack2(h0, h1);
            sptr += Hn * BTOT;

            xa_cur = xa_nxt;
            xb_cur = xb_nxt;
        }
        __syncthreads();
    }
}

// Output projection: out[b][t] = sum_n W_out[n] * h[t][n][b] + b_out.
// Fully parallel, DRAM-bound (measured 40us @ 68% DRAM).
__global__ void __launch_bounds__(BTOT, 2)
out_proj_kernel(const float* __restrict__ W_out,
                const float* __restrict__ b_out,
                float* __restrict__ out)
{
    const int t = blockIdx.x;
    const int b = threadIdx.x;
    float acc = b_out[0];
    const float* __restrict__ hp = &g_hscr[t][0][b];
    #pragma unroll 5
    for (int nn = 0; nn < Hn; ++nn)
        acc = fmaf(W_out[nn], hp[(size_t)nn * BTOT], acc);
    out[b * T_STEPS + t] = acc;
}

extern "C" void kernel_launch(void* const* d_in, const int* in_sizes, int n_in,
                              void* d_out, int out_size) {
    (void)in_sizes; (void)n_in; (void)out_size;
    const float* input = (const float*)d_in[0];
    const float* W_ih  = (const float*)d_in[1];
    const float* W_hh  = (const float*)d_in[2];
    const float* b_ih  = (const float*)d_in[3];
    const float* b_hh  = (const float*)d_in[4];
    const float* W_out = (const float*)d_in[5];
    const float* b_out = (const float*)d_in[6];
    float* out = (float*)d_out;

    lstm_persistent_kernel<<<NBLOCKS, NTHREADS>>>(input, W_ih, W_hh, b_ih, b_hh);
    out_proj_kernel<<<T_STEPS, BTOT>>>(W_out, b_out, out);
}